// round 3
// baseline (speedup 1.0000x reference)
#include <cuda_runtime.h>
#include <math.h>

// ---------------------------------------------------------------------------
// MoEGate: logits = X @ W^T, softmax, top-8 (+renorm), seq-aux loss.
//   X: [N=32768, 2048] f32     W: [64, 2048] f32
//   out (f32): [ topk_idx (N*8, as float) | topk_weight (N*8) | aux_loss (1) ]
// ---------------------------------------------------------------------------

#define DIM      2048
#define EXPERTS  64
#define TOPK     8
#define MT       128     // tokens per CTA
#define KC       32      // k-chunk
#define NTHREADS 256
#define BSZ      4

// Deterministic per-CTA partials (each CTA writes its own row; no atomics,
// no init needed — fully overwritten every launch).
__device__ float g_score_partial[1024 * EXPERTS];
__device__ int   g_count_partial[1024 * EXPERTS];

__global__ __launch_bounds__(NTHREADS, 2)
void moe_gate_main(const float* __restrict__ X,
                   const float* __restrict__ W,
                   float* __restrict__ out,
                   int n_tokens)
{
    __shared__ union {
        struct {                       // GEMM phase (exactly 48 KB)
            float xs[2][KC][MT];       // x tile, transposed: [k][token]
            float ws[2][KC][EXPERTS];  // w tile, transposed: [k][expert]
        } gm;
        struct {                       // epilogue phase (aliases gm)
            float scores[MT][EXPERTS + 1];  // +1 pad -> conflict-free column/row walks
            int   cnt[EXPERTS];
        } ep;
    } sm;

    const int tid  = threadIdx.x;
    const int tg   = tid & 15;         // token group: tokens tg*8 .. tg*8+7
    const int eg   = tid >> 4;         // expert group: experts eg*4 .. eg*4+3
    const int tok0 = blockIdx.x * MT;

    float acc[8][4];
#pragma unroll
    for (int i = 0; i < 8; i++)
#pragma unroll
        for (int j = 0; j < 4; j++) acc[i][j] = 0.0f;

    const float4* __restrict__ X4 = reinterpret_cast<const float4*>(X);
    const float4* __restrict__ W4 = reinterpret_cast<const float4*>(W);

    // Global-load mapping: 8 consecutive threads read 8 consecutive float4 of
    // one row (coalesced 128B).
    const int lrow = tid >> 3;   // 0..31
    const int lkq  = tid & 7;    // 0..7  (float4 index within the 32-float chunk)

    const int NCHUNK = DIM / KC; // 64
    float4 rx[4], rw[2];

    // ---- prologue: load chunk 0 into buffer 0 -----------------------------
    {
        const int k4 = 0;
#pragma unroll
        for (int i = 0; i < 4; i++)
            rx[i] = X4[(size_t)(tok0 + lrow + i * 32) * (DIM / 4) + k4 + lkq];
#pragma unroll
        for (int i = 0; i < 2; i++)
            rw[i] = W4[(size_t)(lrow + i * 32) * (DIM / 4) + k4 + lkq];
#pragma unroll
        for (int i = 0; i < 4; i++) {
            const int t = lrow + i * 32;
            sm.gm.xs[0][lkq * 4 + 0][t] = rx[i].x;
            sm.gm.xs[0][lkq * 4 + 1][t] = rx[i].y;
            sm.gm.xs[0][lkq * 4 + 2][t] = rx[i].z;
            sm.gm.xs[0][lkq * 4 + 3][t] = rx[i].w;
        }
#pragma unroll
        for (int i = 0; i < 2; i++) {
            const int e = lrow + i * 32;
            sm.gm.ws[0][lkq * 4 + 0][e] = rw[i].x;
            sm.gm.ws[0][lkq * 4 + 1][e] = rw[i].y;
            sm.gm.ws[0][lkq * 4 + 2][e] = rw[i].z;
            sm.gm.ws[0][lkq * 4 + 3][e] = rw[i].w;
        }
    }
    __syncthreads();

    // ---- main loop: LDG(next) | FFMA(cur) | STS(next) | sync --------------
    for (int c = 0; c < NCHUNK; c++) {
        const int cur = c & 1;
        const int nxt = cur ^ 1;

        if (c + 1 < NCHUNK) {
            const int k4 = (c + 1) * (KC / 4);
#pragma unroll
            for (int i = 0; i < 4; i++)
                rx[i] = X4[(size_t)(tok0 + lrow + i * 32) * (DIM / 4) + k4 + lkq];
#pragma unroll
            for (int i = 0; i < 2; i++)
                rw[i] = W4[(size_t)(lrow + i * 32) * (DIM / 4) + k4 + lkq];
        }

        const float4* xs4 = reinterpret_cast<const float4*>(&sm.gm.xs[cur][0][0]);
        const float4* ws4 = reinterpret_cast<const float4*>(&sm.gm.ws[cur][0][0]);
#pragma unroll 8
        for (int kk = 0; kk < KC; kk++) {
            const float4 x0 = xs4[kk * (MT / 4) + tg * 2];
            const float4 x1 = xs4[kk * (MT / 4) + tg * 2 + 1];
            const float4 w  = ws4[kk * (EXPERTS / 4) + eg];
            const float xv[8] = {x0.x, x0.y, x0.z, x0.w, x1.x, x1.y, x1.z, x1.w};
            const float wv[4] = {w.x, w.y, w.z, w.w};
#pragma unroll
            for (int i = 0; i < 8; i++)
#pragma unroll
                for (int j = 0; j < 4; j++)
                    acc[i][j] = fmaf(xv[i], wv[j], acc[i][j]);
        }

        if (c + 1 < NCHUNK) {
#pragma unroll
            for (int i = 0; i < 4; i++) {
                const int t = lrow + i * 32;
                sm.gm.xs[nxt][lkq * 4 + 0][t] = rx[i].x;
                sm.gm.xs[nxt][lkq * 4 + 1][t] = rx[i].y;
                sm.gm.xs[nxt][lkq * 4 + 2][t] = rx[i].z;
                sm.gm.xs[nxt][lkq * 4 + 3][t] = rx[i].w;
            }
#pragma unroll
            for (int i = 0; i < 2; i++) {
                const int e = lrow + i * 32;
                sm.gm.ws[nxt][lkq * 4 + 0][e] = rw[i].x;
                sm.gm.ws[nxt][lkq * 4 + 1][e] = rw[i].y;
                sm.gm.ws[nxt][lkq * 4 + 2][e] = rw[i].z;
                sm.gm.ws[nxt][lkq * 4 + 3][e] = rw[i].w;
            }
        }
        __syncthreads();
    }

    // ---- epilogue: logits -> smem (re-using GEMM smem) --------------------
#pragma unroll
    for (int i = 0; i < 8; i++)
#pragma unroll
        for (int j = 0; j < 4; j++)
            sm.ep.scores[tg * 8 + i][eg * 4 + j] = acc[i][j];
    if (tid < EXPERTS) sm.ep.cnt[tid] = 0;
    __syncthreads();

    // softmax per token (row walk: stride 65 -> conflict-free)
    if (tid < MT) {
        float* row = sm.ep.scores[tid];
        float m = -INFINITY;
#pragma unroll 8
        for (int e = 0; e < EXPERTS; e++) m = fmaxf(m, row[e]);
        float s = 0.0f;
#pragma unroll 8
        for (int e = 0; e < EXPERTS; e++) {
            const float p = expf(row[e] - m);
            s += p;
            row[e] = p;
        }
        const float inv = 1.0f / s;   // monotone scaling: identical ordering to ref
#pragma unroll 8
        for (int e = 0; e < EXPERTS; e++) row[e] *= inv;
    }
    __syncthreads();

    // per-expert score sums over this CTA's 128 tokens (column walk: stride
    // 65 -> banks skewed, conflict-free). Deterministic (no atomics).
    if (tid < EXPERTS) {
        float s = 0.0f;
#pragma unroll 8
        for (int t = 0; t < MT; t++) s += sm.ep.scores[t][tid];
        g_score_partial[blockIdx.x * EXPERTS + tid] = s;
    }
    __syncthreads();   // sums must finish before top-8 destroys rows

    // top-8 per token: strict '>' argmax == jax.lax.top_k stable descending
    if (tid < MT) {
        float* row = sm.ep.scores[tid];
        float wsel[TOPK];
        int   isel[TOPK];
        float ssum = 0.0f;
#pragma unroll
        for (int r = 0; r < TOPK; r++) {
            float best = -1.0f;
            int   bi   = 0;
#pragma unroll 8
            for (int e = 0; e < EXPERTS; e++) {
                const float v = row[e];
                if (v > best) { best = v; bi = e; }
            }
            wsel[r] = best;
            isel[r] = bi;
            ssum   += best;
            row[bi] = -2.0f;                // exclude (scores are positive)
            atomicAdd(&sm.ep.cnt[bi], 1);   // integer smem atomic: deterministic
        }
        const float invw = 1.0f / (ssum + 1e-20f);
        const int tokG = tok0 + tid;
        float* out_idx = out + (size_t)tokG * TOPK;
        float* out_w   = out + (size_t)n_tokens * TOPK + (size_t)tokG * TOPK;
#pragma unroll
        for (int r = 0; r < TOPK; r++) {
            out_idx[r] = (float)isel[r];
            out_w[r]   = wsel[r] * invw;
        }
    }
    __syncthreads();
    if (tid < EXPERTS)
        g_count_partial[blockIdx.x * EXPERTS + tid] = sm.ep.cnt[tid];
}

// ---------------------------------------------------------------------------
// aux loss: ce[b,e] * mean_scores[b,e], summed, /bsz * alpha. One block,
// fixed-order reduction -> deterministic.
// ---------------------------------------------------------------------------
__global__ void moe_gate_aux(float* __restrict__ out, int n_tokens,
                             int ctas_per_batch)
{
    const int tid = threadIdx.x;        // 256 = BSZ * EXPERTS
    const int b = tid >> 6;
    const int e = tid & 63;

    float s = 0.0f;
    int   c = 0;
    for (int i = 0; i < ctas_per_batch; i++) {
        const int row = b * ctas_per_batch + i;
        s += g_score_partial[row * EXPERTS + e];
        c += g_count_partial[row * EXPERTS + e];
    }
    const int   seq  = n_tokens / BSZ;                       // 8192
    const float mean = s / (float)seq;
    const float ce   = (float)c * ((float)EXPERTS / (float)(seq * TOPK));
    float contrib = ce * mean;

    __shared__ float red[256];
    red[tid] = contrib;
    __syncthreads();
    for (int st = 128; st > 0; st >>= 1) {
        if (tid < st) red[tid] += red[tid + st];
        __syncthreads();
    }
    if (tid == 0)
        out[(size_t)n_tokens * 2 * TOPK] = red[0] * (0.1f / (float)BSZ);
}

// ---------------------------------------------------------------------------
extern "C" void kernel_launch(void* const* d_in, const int* in_sizes, int n_in,
                              void* d_out, int out_size)
{
    const float* X = (const float*)d_in[0];   // hidden_states [4,8192,2048]
    const float* W = (const float*)d_in[1];   // weight        [64,2048]
    float* out = (float*)d_out;

    const int n_tokens = in_sizes[0] / DIM;   // 32768
    const int n_cta    = n_tokens / MT;       // 256
    const int ctas_per_batch = n_cta / BSZ;   // 64

    moe_gate_main<<<n_cta, NTHREADS>>>(X, W, out, n_tokens);
    moe_gate_aux<<<1, BSZ * EXPERTS>>>(out, n_tokens, ctas_per_batch);
}